// round 15
// baseline (speedup 1.0000x reference)
#include <cuda_runtime.h>

#define BB    64
#define TTT   512
#define IN    512
#define HH    1024
#define G4    4096
#define NSTEP 1024
#define KC    64
#define NCH_S (HH / KC)   // 16
#define NCH_P (IN / KC)   // 8
#define NCTA  128
#define SHH   68          // sh_h row stride (floats); rows 16B-aligned
#define SUU   36          // sh_u row stride (floats); rows 16B-aligned
#define WS    2176        // reduction warp-region stride (floats) = 32*68
#define SMEM_BYTES (16 * WS * 4)   // 139264 B

// 512 MB scratch for G[t][b][4096] = x_t @ Ww^T + (bw + bu)
__device__ float g_G[(size_t)TTT * BB * G4];

// grid-barrier state
__device__ unsigned g_cnt;
__device__ volatile unsigned g_gen;

__device__ __forceinline__ unsigned long long fma2(unsigned long long a,
                                                   unsigned long long b,
                                                   unsigned long long c) {
    unsigned long long d;
    asm("fma.rn.f32x2 %0, %1, %2, %3;" : "=l"(d) : "l"(a), "l"(b), "l"(c));
    return d;
}
__device__ __forceinline__ unsigned long long addf2(unsigned long long a,
                                                    unsigned long long b) {
    unsigned long long d;
    asm("add.rn.f32x2 %0, %1, %2;" : "=l"(d) : "l"(a), "l"(b));
    return d;
}
__device__ __forceinline__ unsigned long long dup2(float v) {
    unsigned int u = __float_as_uint(v);
    unsigned long long d;
    asm("mov.b64 %0, {%1, %1};" : "=l"(d) : "r"(u));
    return d;
}
__device__ __forceinline__ float lo2(unsigned long long v) {
    return __uint_as_float((unsigned)v);
}
__device__ __forceinline__ float hi2(unsigned long long v) {
    return __uint_as_float((unsigned)(v >> 32));
}
__device__ __forceinline__ float sigm(float x) { return 1.f / (1.f + __expf(-x)); }

__device__ __forceinline__ void grid_barrier(int tid) {
    __syncthreads();
    if (tid == 0) {
        __threadfence();
        unsigned gen = g_gen;
        if (atomicAdd(&g_cnt, 1u) == NCTA - 1) {
            g_cnt = 0;
            __threadfence();
            g_gen = gen + 1;
        } else {
            while (g_gen == gen) { }
        }
        __threadfence();
    }
    __syncthreads();
}

// one k value for one warp: 2 LDS.128 h (4-lane broadcast, 2 wf each),
// 2 LDS.128 u (8-lane broadcast, 1 wf each), 8 dup2, 32 fma.rn.f32x2
#define MICRO_K(hk, uk, acc)                                                   \
    do {                                                                       \
        float4 h0 = *(const float4*)(hk);                                      \
        float4 h1 = *(const float4*)((hk) + 4);                                \
        ulonglong2 u0 = *(const ulonglong2*)(uk);                              \
        ulonglong2 u1 = *(const ulonglong2*)((uk) + 4);                        \
        float hm[8] = {h0.x, h0.y, h0.z, h0.w, h1.x, h1.y, h1.z, h1.w};        \
        _Pragma("unroll")                                                      \
        for (int m = 0; m < 8; m++) {                                          \
            unsigned long long hd = dup2(hm[m]);                               \
            acc[m][0] = fma2(hd, u0.x, acc[m][0]);                             \
            acc[m][1] = fma2(hd, u0.y, acc[m][1]);                             \
            acc[m][2] = fma2(hd, u1.x, acc[m][2]);                             \
            acc[m][3] = fma2(hd, u1.y, acc[m][3]);                             \
        }                                                                      \
    } while (0)

// ---------------------------------------------------------------------------
// Persistent scan: 128 CTAs x 512 threads, s = 0..1023.
// Warp w = k-slice (k mod 16 == w); its lanes tile the full 64x32 output
// (8 mg x 4 ng, 8Mx8N each). KC=64 double-buffered staging; 16 per-warp
// partials combined by one-shot smem reduction; fused LSTM pointwise.
// ---------------------------------------------------------------------------
__global__ __launch_bounds__(512, 1) void lstm_scan(const float* __restrict__ Uw,
                                                    float* __restrict__ out) {
    extern __shared__ __align__(16) float sm[];
    float* sh_h = sm;            // 2 * 64 * 68 = 8704 floats
    float* sh_u = sm + 8704;     // 2 * 64 * 36 = 4608 floats
    float* red  = sm;            // 16 * 2176 floats (aliases staging)
    float* gb   = sm;            // 64 * 36 floats (aliases red; sync-guarded)

    const int tid  = threadIdx.x;
    const int w    = tid >> 5;          // warp = k-slice
    const int lane = tid & 31;
    const int mg   = lane >> 2, ng = lane & 3;
    const int m0   = 8 * mg,   n0 = 8 * ng;
    const int j0   = blockIdx.x * 8;

    // staging ids: 512 thr = 64 k-rows x 8 groups
    const int sk = tid & 63, sa = tid >> 6;
    int uoffs[4];
#pragma unroll
    for (int i = 0; i < 4; i++) {
        int c = 4 * sa + i;                       // col 0..31
        uoffs[i] = ((c >> 3) * HH + j0 + (c & 7)) * HH + sk;
    }
    const int hstA = sk * SHH + 8 * sa;
    const int ustA = sk * SUU + 4 * sa;

    // pointwise ids
    const int pb = tid >> 3, pu = tid & 7;

    // reduction-gather ids: thread owns (row rb, cols rc0..rc0+3)
    const int rb  = tid >> 3;
    const int rc0 = 4 * (tid & 7);
    const int rl  = (rb >> 3) * 4 + (rc0 >> 3);   // owning lane in each warp
    const int roff = rl * SHH + 8 * (rb & 7) + (rc0 & 7);

    const size_t BH = (size_t)BB * HH;
    const size_t CB = (size_t)NSTEP * BH;

    for (int s = 0; s < NSTEP; s++) {
        // hoisted pointwise operands (DRAM latency hidden behind GEMM)
        const int t = s >> 1;
        float gp[4], cp = 0.f;
        {
            size_t e = ((size_t)(t * BB) + pb) * G4 + j0 + pu;
#pragma unroll
            for (int q = 0; q < 4; q++) gp[q] = __ldcs(&g_G[e + (size_t)q * HH]);
            if (s > 0)
                cp = __ldcs(&out[CB + (size_t)(s - 1) * BH + (size_t)pb * HH + j0 + pu]);
        }

        unsigned long long acc[8][4];
#pragma unroll
        for (int m = 0; m < 8; m++)
#pragma unroll
            for (int p = 0; p < 4; p++) acc[m][p] = 0ull;

        if (s > 0) {
            const float* hp = out + (size_t)(s - 1) * BH;
            float hr[8], ur[4];
            // prologue: chunk 0 -> regs -> buf 0
#pragma unroll
            for (int j = 0; j < 8; j++)
                hr[j] = __ldcs(hp + (8 * sa + j) * HH + sk);
#pragma unroll
            for (int i = 0; i < 4; i++) ur[i] = Uw[uoffs[i]];
            *(float4*)&sh_h[hstA]     = make_float4(hr[0], hr[1], hr[2], hr[3]);
            *(float4*)&sh_h[hstA + 4] = make_float4(hr[4], hr[5], hr[6], hr[7]);
            *(float4*)&sh_u[ustA]     = make_float4(ur[0], ur[1], ur[2], ur[3]);

            int buf = 0;
            for (int ch = 0; ch < NCH_S; ch++) {
                __syncthreads();
                if (ch + 1 < NCH_S) {
                    int kc = (ch + 1) * KC;
#pragma unroll
                    for (int j = 0; j < 8; j++)
                        hr[j] = __ldcs(hp + (8 * sa + j) * HH + kc + sk);
#pragma unroll
                    for (int i = 0; i < 4; i++) ur[i] = Uw[uoffs[i] + kc];
                }
                const float* hbp = sh_h + buf * (KC * SHH);
                const float* ubp = sh_u + buf * (KC * SUU);
#pragma unroll
                for (int jj = 0; jj < 4; jj++) {
                    int k = w + 16 * jj;
                    MICRO_K(hbp + k * SHH + m0, ubp + k * SUU + n0, acc);
                }
                if (ch + 1 < NCH_S) {
                    int nb = buf ^ 1;
                    *(float4*)&sh_h[nb * (KC * SHH) + hstA] =
                        make_float4(hr[0], hr[1], hr[2], hr[3]);
                    *(float4*)&sh_h[nb * (KC * SHH) + hstA + 4] =
                        make_float4(hr[4], hr[5], hr[6], hr[7]);
                    *(float4*)&sh_u[nb * (KC * SUU) + ustA] =
                        make_float4(ur[0], ur[1], ur[2], ur[3]);
                }
                buf ^= 1;
            }
        }

        // ---- cross-warp reduction over the 16 k-slice partials ----
        __syncthreads();  // staging reads done; red may overwrite
        {
            float* rw = red + w * WS + lane * SHH;
#pragma unroll
            for (int r = 0; r < 8; r++) {
                *(ulonglong2*)(rw + 8 * r)     = make_ulonglong2(acc[r][0], acc[r][1]);
                *(ulonglong2*)(rw + 8 * r + 4) = make_ulonglong2(acc[r][2], acc[r][3]);
            }
        }
        __syncthreads();
        unsigned long long s0 = 0ull, s1 = 0ull;
#pragma unroll
        for (int wi = 0; wi < 16; wi++) {
            ulonglong2 v = *(const ulonglong2*)&red[wi * WS + roff];
            s0 = addf2(s0, v.x);
            s1 = addf2(s1, v.y);
        }
        __syncthreads();  // red reads done; gb may overwrite
        *(ulonglong2*)&gb[rb * SUU + rc0] = make_ulonglong2(s0, s1);
        __syncthreads();

        // ---- fused pointwise LSTM update (one (batch, unit) per thread) ----
        {
            float gi = gb[pb * SUU + pu]      + gp[0];
            float gf = gb[pb * SUU + 8 + pu]  + gp[1];
            float gg = gb[pb * SUU + 16 + pu] + gp[2];
            float go = gb[pb * SUU + 24 + pu] + gp[3];
            float cn = cp * sigm(gf) + sigm(gi) * tanhf(gg);
            float hn = sigm(go) * tanhf(cn);
            size_t o = (size_t)s * BH + (size_t)pb * HH + j0 + pu;
            out[o] = hn;
            out[CB + o] = cn;
        }

        grid_barrier(tid);  // also guards gb (aliases sh_h) vs next staging
    }
}

// ---------------------------------------------------------------------------
// Precompute: G[t][b][n] = bias[n] + sum_k x[b][t][k] * Ww[n][k]
// Grid (128 n-groups of 32, 512 t) x 512 threads; same micro-kernel, K=512.
// ---------------------------------------------------------------------------
__global__ __launch_bounds__(512, 1) void lstm_pre(const float* __restrict__ x,
                                                   const float* __restrict__ Ww,
                                                   const float* __restrict__ bw,
                                                   const float* __restrict__ bu) {
    extern __shared__ __align__(16) float sm[];
    float* sh_h = sm;
    float* sh_u = sm + 8704;
    float* red  = sm;

    const int tid  = threadIdx.x;
    const int w    = tid >> 5;
    const int lane = tid & 31;
    const int mg   = lane >> 2, ng = lane & 3;
    const int m0   = 8 * mg,   n0 = 8 * ng;
    const int n0g  = blockIdx.x * 32;
    const int t    = blockIdx.y;

    const int sk = tid & 63, sa = tid >> 6;
    int uoffs[4];
#pragma unroll
    for (int i = 0; i < 4; i++)
        uoffs[i] = (n0g + 4 * sa + i) * IN + sk;
    const int hstA = sk * SHH + 8 * sa;
    const int ustA = sk * SUU + 4 * sa;

    const int rb  = tid >> 3;
    const int rc0 = 4 * (tid & 7);
    const int rl  = (rb >> 3) * 4 + (rc0 >> 3);
    const int roff = rl * SHH + 8 * (rb & 7) + (rc0 & 7);

    unsigned long long acc[8][4];
#pragma unroll
    for (int m = 0; m < 8; m++)
#pragma unroll
        for (int p = 0; p < 4; p++) acc[m][p] = 0ull;

    float hr[8], ur[4];
#pragma unroll
    for (int j = 0; j < 8; j++)
        hr[j] = __ldcs(&x[((size_t)(8 * sa + j) * TTT + t) * IN + sk]);
#pragma unroll
    for (int i = 0; i < 4; i++) ur[i] = Ww[uoffs[i]];
    *(float4*)&sh_h[hstA]     = make_float4(hr[0], hr[1], hr[2], hr[3]);
    *(float4*)&sh_h[hstA + 4] = make_float4(hr[4], hr[5], hr[6], hr[7]);
    *(float4*)&sh_u[ustA]     = make_float4(ur[0], ur[1], ur[2], ur[3]);

    int buf = 0;
    for (int ch = 0; ch < NCH_P; ch++) {
        __syncthreads();
        if (ch + 1 < NCH_P) {
            int kc = (ch + 1) * KC;
#pragma unroll
            for (int j = 0; j < 8; j++)
                hr[j] = __ldcs(&x[((size_t)(8 * sa + j) * TTT + t) * IN + kc + sk]);
#pragma unroll
            for (int i = 0; i < 4; i++) ur[i] = Ww[uoffs[i] + kc];
        }
        const float* hbp = sh_h + buf * (KC * SHH);
        const float* ubp = sh_u + buf * (KC * SUU);
#pragma unroll
        for (int jj = 0; jj < 4; jj++) {
            int k = w + 16 * jj;
            MICRO_K(hbp + k * SHH + m0, ubp + k * SUU + n0, acc);
        }
        if (ch + 1 < NCH_P) {
            int nb = buf ^ 1;
            *(float4*)&sh_h[nb * (KC * SHH) + hstA] =
                make_float4(hr[0], hr[1], hr[2], hr[3]);
            *(float4*)&sh_h[nb * (KC * SHH) + hstA + 4] =
                make_float4(hr[4], hr[5], hr[6], hr[7]);
            *(float4*)&sh_u[nb * (KC * SUU) + ustA] =
                make_float4(ur[0], ur[1], ur[2], ur[3]);
        }
        buf ^= 1;
    }

    __syncthreads();
    {
        float* rw = red + w * WS + lane * SHH;
#pragma unroll
        for (int r = 0; r < 8; r++) {
            *(ulonglong2*)(rw + 8 * r)     = make_ulonglong2(acc[r][0], acc[r][1]);
            *(ulonglong2*)(rw + 8 * r + 4) = make_ulonglong2(acc[r][2], acc[r][3]);
        }
    }
    __syncthreads();
    unsigned long long s0 = 0ull, s1 = 0ull;
#pragma unroll
    for (int wi = 0; wi < 16; wi++) {
        ulonglong2 v = *(const ulonglong2*)&red[wi * WS + roff];
        s0 = addf2(s0, v.x);
        s1 = addf2(s1, v.y);
    }

    {
        int n = n0g + rc0;
        float4 r;
        r.x = lo2(s0) + bw[n]     + bu[n];
        r.y = hi2(s0) + bw[n + 1] + bu[n + 1];
        r.z = lo2(s1) + bw[n + 2] + bu[n + 2];
        r.w = hi2(s1) + bw[n + 3] + bu[n + 3];
        *(float4*)&g_G[((size_t)t * BB + rb) * G4 + n] = r;
    }
}

extern "C" void kernel_launch(void* const* d_in, const int* in_sizes, int n_in,
                              void* d_out, int out_size) {
    const float* x  = (const float*)d_in[0];
    const float* Ww = (const float*)d_in[1];
    const float* bw = (const float*)d_in[2];
    const float* Uw = (const float*)d_in[3];
    const float* bu = (const float*)d_in[4];
    float* out = (float*)d_out;

    (void)in_sizes; (void)n_in; (void)out_size;

    cudaFuncSetAttribute(lstm_pre,  cudaFuncAttributeMaxDynamicSharedMemorySize,
                         SMEM_BYTES);
    cudaFuncSetAttribute(lstm_scan, cudaFuncAttributeMaxDynamicSharedMemorySize,
                         SMEM_BYTES);

    lstm_pre<<<dim3(128, 512), 512, SMEM_BYTES>>>(x, Ww, bw, bu);
    lstm_scan<<<NCTA, 512, SMEM_BYTES>>>(Uw, out);
}

// round 16
// speedup vs baseline: 1.0533x; 1.0533x over previous
#include <cuda_runtime.h>

#define BB    64
#define TTT   512
#define IN    512
#define HH    1024
#define G4    4096
#define NSTEP 1024
#define NCTA  128

// ---- scan kernel smem layout (floats) ----
#define SHH   68                  // h staging row stride
#define HBUF  (64 * SHH)          // 4352 floats per h buffer
#define RWS   2176                // reduction region per warp = 32 lanes * 68
#define UWOFF 17408               // = 2*HBUF + pad -> start of persistent Uw
#define SMEM_SCAN ((UWOFF + 1024 * 32) * 4)   // 200704 B

// ---- pre kernel (R15 layout) ----
#define KCP   64
#define SUU   36
#define WSP   2176
#define SMEM_PRE (16 * WSP * 4)   // 139264 B

// 512 MB scratch for G[t][b][4096] = x_t @ Ww^T + (bw + bu)
__device__ float g_G[(size_t)TTT * BB * G4];

// grid-barrier state
__device__ unsigned g_cnt;
__device__ volatile unsigned g_gen;

__device__ __forceinline__ unsigned long long fma2(unsigned long long a,
                                                   unsigned long long b,
                                                   unsigned long long c) {
    unsigned long long d;
    asm("fma.rn.f32x2 %0, %1, %2, %3;" : "=l"(d) : "l"(a), "l"(b), "l"(c));
    return d;
}
__device__ __forceinline__ unsigned long long addf2(unsigned long long a,
                                                    unsigned long long b) {
    unsigned long long d;
    asm("add.rn.f32x2 %0, %1, %2;" : "=l"(d) : "l"(a), "l"(b));
    return d;
}
__device__ __forceinline__ unsigned long long dup2(float v) {
    unsigned int u = __float_as_uint(v);
    unsigned long long d;
    asm("mov.b64 %0, {%1, %1};" : "=l"(d) : "r"(u));
    return d;
}
__device__ __forceinline__ float lo2(unsigned long long v) {
    return __uint_as_float((unsigned)v);
}
__device__ __forceinline__ float hi2(unsigned long long v) {
    return __uint_as_float((unsigned)(v >> 32));
}
__device__ __forceinline__ float sigm(float x) { return 1.f / (1.f + __expf(-x)); }

__device__ __forceinline__ void grid_barrier(int tid) {
    __syncthreads();
    if (tid == 0) {
        __threadfence();
        unsigned gen = g_gen;
        if (atomicAdd(&g_cnt, 1u) == NCTA - 1) {
            g_cnt = 0;
            __threadfence();
            g_gen = gen + 1;
        } else {
            while (g_gen == gen) { }
        }
        __threadfence();
    }
    __syncthreads();
}

// one k for one warp: 2 LDS.128 h (swizzled, 1 wf each), 2 LDS.128 u
// (broadcast, 1 wf each), 8 dup2, 32 fma.rn.f32x2
#define MICRO_K(hk, uk, acc)                                                   \
    do {                                                                       \
        float4 h0 = *(const float4*)(hk);                                      \
        float4 h1 = *(const float4*)((hk) + 4);                                \
        ulonglong2 u0 = *(const ulonglong2*)(uk);                              \
        ulonglong2 u1 = *(const ulonglong2*)((uk) + 4);                        \
        float hm[8] = {h0.x, h0.y, h0.z, h0.w, h1.x, h1.y, h1.z, h1.w};        \
        _Pragma("unroll")                                                      \
        for (int m = 0; m < 8; m++) {                                          \
            unsigned long long hd = dup2(hm[m]);                               \
            acc[m][0] = fma2(hd, u0.x, acc[m][0]);                             \
            acc[m][1] = fma2(hd, u0.y, acc[m][1]);                             \
            acc[m][2] = fma2(hd, u1.x, acc[m][2]);                             \
            acc[m][3] = fma2(hd, u1.y, acc[m][3]);                             \
        }                                                                      \
    } while (0)

// ---------------------------------------------------------------------------
// Persistent scan: 128 CTAs x 512 threads, s = 0..1023.
// Uw slice (32 gate-cols x 1024 k = 128 KB) loaded ONCE into smem.
// Warp w = k-slice (k mod 16 == w); lanes tile the 64x32 output (8Mx8N each).
// h staged per 64-k chunk (double-buffered, swizzled rows). 16 per-warp
// partials combined by a two-pass smem reduction; fused LSTM pointwise.
// ---------------------------------------------------------------------------
__global__ __launch_bounds__(512, 1) void lstm_scan(const float* __restrict__ Uw,
                                                    float* __restrict__ out) {
    extern __shared__ __align__(16) float sm[];
    float* sh_h  = sm;              // 2 x HBUF (aliased by red/gb, sync-guarded)
    float* red   = sm;              // 8 x RWS
    float* gb    = sm;              // 64 x 36
    float* sh_uw = sm + UWOFF;      // [k*32 + c], 1024 x 32

    const int tid  = threadIdx.x;
    const int w    = tid >> 5;
    const int lane = tid & 31;
    const int mg   = lane >> 2, ng = lane & 3;
    const int n0   = 8 * ng;
    const int j0   = blockIdx.x * 8;

    // --- one-time persistent Uw load: sh_uw[k*32 + c] = Uw[nglob(c)][k] ---
    for (int i = 0; i < 64; i++) {
        int idx = i * 512 + tid;
        int k = idx & 1023, c = idx >> 10;
        int nglob = (c >> 3) * HH + j0 + (c & 7);
        sh_uw[k * 32 + c] = Uw[(size_t)nglob * HH + k];
    }

    // staging ids: 512 thr = 64 k-rows x 8 m-groups; swizzled STS offset
    const int sk = tid & 63, sa = tid >> 6;
    const int hstoff = sk * SHH + 8 * sa + 4 * (sa >> 2);
    // inner h read offset (swizzled)
    const int hrd = 8 * mg + 4 * (mg >> 2);

    // pointwise ids
    const int pb = tid >> 3, pu = tid & 7;

    // reduction-gather ids: thread owns (row rb, cols rc0..rc0+3)
    const int rb  = tid >> 3;
    const int rc0 = 4 * (tid & 7);
    const int rl  = (rb >> 3) * 4 + (rc0 >> 3);
    const int roff = rl * SHH + (rb & 7) * 8 + (rc0 & 7);

    const size_t BH = (size_t)BB * HH;
    const size_t CB = (size_t)NSTEP * BH;

    __syncthreads();  // sh_uw ready

    for (int s = 0; s < NSTEP; s++) {
        // hoisted pointwise operands (latency hidden behind GEMM)
        const int t = s >> 1;
        float gp[4], cp = 0.f;
        {
            size_t e = ((size_t)(t * BB) + pb) * G4 + j0 + pu;
#pragma unroll
            for (int q = 0; q < 4; q++) gp[q] = __ldcs(&g_G[e + (size_t)q * HH]);
            if (s > 0)
                cp = __ldcs(&out[CB + (size_t)(s - 1) * BH + (size_t)pb * HH + j0 + pu]);
        }

        unsigned long long acc[8][4];
#pragma unroll
        for (int m = 0; m < 8; m++)
#pragma unroll
            for (int p = 0; p < 4; p++) acc[m][p] = 0ull;

        if (s > 0) {
            const float* hp = out + (size_t)(s - 1) * BH;
            float hr[8];
            // prologue: chunk 0 -> regs -> buf 0
#pragma unroll
            for (int j = 0; j < 8; j++)
                hr[j] = __ldcs(hp + (8 * sa + j) * HH + sk);
            *(float4*)&sh_h[hstoff]     = make_float4(hr[0], hr[1], hr[2], hr[3]);
            *(float4*)&sh_h[hstoff + 4] = make_float4(hr[4], hr[5], hr[6], hr[7]);

            int buf = 0;
            for (int ch = 0; ch < 16; ch++) {
                __syncthreads();
                if (ch + 1 < 16) {
                    int kc = (ch + 1) * 64;
#pragma unroll
                    for (int j = 0; j < 8; j++)
                        hr[j] = __ldcs(hp + (8 * sa + j) * HH + kc + sk);
                }
                const float* hbp = sh_h + buf * HBUF;
                const float* uwp = sh_uw + (ch * 64) * 32;
#pragma unroll
                for (int jj = 0; jj < 4; jj++) {
                    int kl = w + 16 * jj;
                    MICRO_K(hbp + kl * SHH + hrd, uwp + kl * 32 + n0, acc);
                }
                if (ch + 1 < 16) {
                    int nb = buf ^ 1;
                    *(float4*)&sh_h[nb * HBUF + hstoff] =
                        make_float4(hr[0], hr[1], hr[2], hr[3]);
                    *(float4*)&sh_h[nb * HBUF + hstoff + 4] =
                        make_float4(hr[4], hr[5], hr[6], hr[7]);
                }
                buf ^= 1;
            }
        }

        // ---- two-pass cross-warp reduction (buffer = 8 warp-regions) ----
        unsigned long long s0 = 0ull, s1 = 0ull;
        __syncthreads();  // inner reads + staging done; red may overwrite sh_h
        if (w < 8) {
            float* rw = red + w * RWS + lane * SHH;
#pragma unroll
            for (int m = 0; m < 8; m++) {
                *(ulonglong2*)(rw + 8 * m)     = make_ulonglong2(acc[m][0], acc[m][1]);
                *(ulonglong2*)(rw + 8 * m + 4) = make_ulonglong2(acc[m][2], acc[m][3]);
            }
        }
        __syncthreads();
#pragma unroll
        for (int wi = 0; wi < 8; wi++) {
            ulonglong2 v = *(const ulonglong2*)&red[wi * RWS + roff];
            s0 = addf2(s0, v.x);
            s1 = addf2(s1, v.y);
        }
        __syncthreads();
        if (w >= 8) {
            float* rw = red + (w - 8) * RWS + lane * SHH;
#pragma unroll
            for (int m = 0; m < 8; m++) {
                *(ulonglong2*)(rw + 8 * m)     = make_ulonglong2(acc[m][0], acc[m][1]);
                *(ulonglong2*)(rw + 8 * m + 4) = make_ulonglong2(acc[m][2], acc[m][3]);
            }
        }
        __syncthreads();
#pragma unroll
        for (int wi = 0; wi < 8; wi++) {
            ulonglong2 v = *(const ulonglong2*)&red[wi * RWS + roff];
            s0 = addf2(s0, v.x);
            s1 = addf2(s1, v.y);
        }
        __syncthreads();  // gathers done; gb may overwrite red
        *(ulonglong2*)&gb[rb * 36 + rc0] = make_ulonglong2(s0, s1);
        __syncthreads();

        // ---- fused pointwise LSTM update (one (batch, unit) per thread) ----
        {
            float gi = gb[pb * 36 + pu]      + gp[0];
            float gf = gb[pb * 36 + 8 + pu]  + gp[1];
            float gg = gb[pb * 36 + 16 + pu] + gp[2];
            float go = gb[pb * 36 + 24 + pu] + gp[3];
            float cn = cp * sigm(gf) + sigm(gi) * tanhf(gg);
            float hn = sigm(go) * tanhf(cn);
            size_t o = (size_t)s * BH + (size_t)pb * HH + j0 + pu;
            out[o] = hn;
            out[CB + o] = cn;
        }

        grid_barrier(tid);  // also guards gb (aliases sh_h) vs next staging
    }
}

// ---------------------------------------------------------------------------
// Precompute: G[t][b][n] = bias[n] + sum_k x[b][t][k] * Ww[n][k]
// Grid (128 n-groups of 32, 512 t) x 512 threads; K=512. (R15 version.)
// ---------------------------------------------------------------------------
__global__ __launch_bounds__(512, 1) void lstm_pre(const float* __restrict__ x,
                                                   const float* __restrict__ Ww,
                                                   const float* __restrict__ bw,
                                                   const float* __restrict__ bu) {
    extern __shared__ __align__(16) float sm[];
    float* sh_h = sm;            // 2 * 64 * 68
    float* sh_u = sm + 8704;     // 2 * 64 * 36
    float* red  = sm;

    const int tid  = threadIdx.x;
    const int w    = tid >> 5;
    const int lane = tid & 31;
    const int mg   = lane >> 2, ng = lane & 3;
    const int m0   = 8 * mg,   n0 = 8 * ng;
    const int n0g  = blockIdx.x * 32;
    const int t    = blockIdx.y;

    const int sk = tid & 63, sa = tid >> 6;
    int uoffs[4];
#pragma unroll
    for (int i = 0; i < 4; i++)
        uoffs[i] = (n0g + 4 * sa + i) * IN + sk;
    const int hstA = sk * SHH + 8 * sa;
    const int ustA = sk * SUU + 4 * sa;

    const int rb  = tid >> 3;
    const int rc0 = 4 * (tid & 7);
    const int rl  = (rb >> 3) * 4 + (rc0 >> 3);
    const int roff = rl * SHH + 8 * (rb & 7) + (rc0 & 7);

    unsigned long long acc[8][4];
#pragma unroll
    for (int m = 0; m < 8; m++)
#pragma unroll
        for (int p = 0; p < 4; p++) acc[m][p] = 0ull;

    float hr[8], ur[4];
#pragma unroll
    for (int j = 0; j < 8; j++)
        hr[j] = __ldcs(&x[((size_t)(8 * sa + j) * TTT + t) * IN + sk]);
#pragma unroll
    for (int i = 0; i < 4; i++) ur[i] = Ww[uoffs[i]];
    *(float4*)&sh_h[hstA]     = make_float4(hr[0], hr[1], hr[2], hr[3]);
    *(float4*)&sh_h[hstA + 4] = make_float4(hr[4], hr[5], hr[6], hr[7]);
    *(float4*)&sh_u[ustA]     = make_float4(ur[0], ur[1], ur[2], ur[3]);

    int buf = 0;
    for (int ch = 0; ch < IN / KCP; ch++) {
        __syncthreads();
        if (ch + 1 < IN / KCP) {
            int kc = (ch + 1) * KCP;
#pragma unroll
            for (int j = 0; j < 8; j++)
                hr[j] = __ldcs(&x[((size_t)(8 * sa + j) * TTT + t) * IN + kc + sk]);
#pragma unroll
            for (int i = 0; i < 4; i++) ur[i] = Ww[uoffs[i] + kc];
        }
        const float* hbp = sh_h + buf * (KCP * SHH);
        const float* ubp = sh_u + buf * (KCP * SUU);
#pragma unroll
        for (int jj = 0; jj < 4; jj++) {
            int k = w + 16 * jj;
            MICRO_K(hbp + k * SHH + m0, ubp + k * SUU + n0, acc);
        }
        if (ch + 1 < IN / KCP) {
            int nb = buf ^ 1;
            *(float4*)&sh_h[nb * (KCP * SHH) + hstA] =
                make_float4(hr[0], hr[1], hr[2], hr[3]);
            *(float4*)&sh_h[nb * (KCP * SHH) + hstA + 4] =
                make_float4(hr[4], hr[5], hr[6], hr[7]);
            *(float4*)&sh_u[nb * (KCP * SUU) + ustA] =
                make_float4(ur[0], ur[1], ur[2], ur[3]);
        }
        buf ^= 1;
    }

    __syncthreads();
    {
        float* rw = red + w * WSP + lane * SHH;
#pragma unroll
        for (int m = 0; m < 8; m++) {
            *(ulonglong2*)(rw + 8 * m)     = make_ulonglong2(acc[m][0], acc[m][1]);
            *(ulonglong2*)(rw + 8 * m + 4) = make_ulonglong2(acc[m][2], acc[m][3]);
        }
    }
    __syncthreads();
    unsigned long long s0 = 0ull, s1 = 0ull;
#pragma unroll
    for (int wi = 0; wi < 16; wi++) {
        ulonglong2 v = *(const ulonglong2*)&red[wi * WSP + roff];
        s0 = addf2(s0, v.x);
        s1 = addf2(s1, v.y);
    }

    {
        int n = n0g + rc0;
        float4 r;
        r.x = lo2(s0) + bw[n]     + bu[n];
        r.y = hi2(s0) + bw[n + 1] + bu[n + 1];
        r.z = lo2(s1) + bw[n + 2] + bu[n + 2];
        r.w = hi2(s1) + bw[n + 3] + bu[n + 3];
        *(float4*)&g_G[((size_t)t * BB + rb) * G4 + n] = r;
    }
}

extern "C" void kernel_launch(void* const* d_in, const int* in_sizes, int n_in,
                              void* d_out, int out_size) {
    const float* x  = (const float*)d_in[0];
    const float* Ww = (const float*)d_in[1];
    const float* bw = (const float*)d_in[2];
    const float* Uw = (const float*)d_in[3];
    const float* bu = (const float*)d_in[4];
    float* out = (float*)d_out;

    (void)in_sizes; (void)n_in; (void)out_size;

    cudaFuncSetAttribute(lstm_pre,  cudaFuncAttributeMaxDynamicSharedMemorySize,
                         SMEM_PRE);
    cudaFuncSetAttribute(lstm_scan, cudaFuncAttributeMaxDynamicSharedMemorySize,
                         SMEM_SCAN);

    lstm_pre<<<dim3(128, 512), 512, SMEM_PRE>>>(x, Ww, bw, bu);
    lstm_scan<<<NCTA, 512, SMEM_SCAN>>>(Uw, out);
}